// round 10
// baseline (speedup 1.0000x reference)
#include <cuda_runtime.h>

// CRF negative log-likelihood, L=64 live states, exp-domain recursion,
// 2-way split-K matvec (pair lanes l and l^16 each sum half the states).
//
//   v_t[j]  = (sum_i v_{t-1}[i] * E[i][j]) * exp(pred[b,t-1,j]) * 2^{-ex_t}
//   E[i][j] = exp(trans[i][j]);  ex_t = float exponent of v_{t-1}[0]
//   logZ_b  = m0 + ks*ln2 + log( sum_j v_seq[j] * exp(trans[j][65]) )
//   gold_b  = sum_t pred[b,t,ref_t] + trans[64][ref_0]
//           + sum trans[ref_{t-1}][ref_t] + trans[ref_{seq-1}][65]
//
// 128 threads per batch (grid=B): warp w, lane l handles state
// j = w*16 + (l&15), summing input half h = l>>4 (floats [32h,32h+32) =
// ulonglong2 indices [8h, 8h+8)). SHFL_XOR(16) combines the halves.

__device__ double g_partial[4096];
__device__ int    g_count;   // static zero-init; last CTA resets each run

__device__ __forceinline__ float warp_rmax(float v) {
#pragma unroll
    for (int o = 16; o > 0; o >>= 1)
        v = fmaxf(v, __shfl_xor_sync(0xffffffffu, v, o));
    return v;
}
__device__ __forceinline__ float warp_rsum(float v) {
#pragma unroll
    for (int o = 16; o > 0; o >>= 1)
        v += __shfl_xor_sync(0xffffffffu, v, o);
    return v;
}

typedef unsigned long long u64;
__device__ __forceinline__ u64 ffma2(u64 a, u64 b, u64 c) {
    u64 d;
    asm("fma.rn.f32x2 %0, %1, %2, %3;" : "=l"(d) : "l"(a), "l"(b), "l"(c));
    return d;
}
__device__ __forceinline__ u64 fadd2(u64 a, u64 b) {
    u64 d;
    asm("add.rn.f32x2 %0, %1, %2;" : "=l"(d) : "l"(a), "l"(b));
    return d;
}
__device__ __forceinline__ u64 pack2(float lo, float hi) {
    u64 d;
    asm("mov.b64 %0, {%1, %2};" : "=l"(d) : "f"(lo), "f"(hi));
    return d;
}

__global__ void __launch_bounds__(128, 2)
crf_kernel(const float* __restrict__ pred,
           const float* __restrict__ trans,
           const int*   __restrict__ ref,
           const int*   __restrict__ slen,
           float* __restrict__ out,
           int B, int T, int out_size)
{
    __shared__ float4 e[2][16];     // double-buffered v vector (64 floats)
    __shared__ float  fin[8];
    __shared__ double red[128];
    __shared__ int    s_last;

    const int tid  = threadIdx.x;
    const int w    = tid >> 5;
    const int lane = tid & 31;
    const int h    = lane >> 4;                // input half this lane sums
    const int j    = (w << 4) | (lane & 15);   // owned output state
    const int b    = blockIdx.x;               // grid = B exactly

    const float* pb  = pred + (size_t)b * T * 64;
    const int*   rb  = ref  + (size_t)b * T;
    const int    seq = slen[b];

    // E rows [32h, 32h+32) for column j: 16 packed f32x2 pairs
    u64 E2[16];
#pragma unroll
    for (int p = 0; p < 16; ++p) {
        int i = 32 * h + 2 * p;
        E2[p] = pack2(__expf(trans[i * 66 + j]),
                      __expf(trans[(i + 1) * 66 + j]));
    }

    // ---- gold path score (all 128 threads, distinct time steps) ----
    float gold = 0.0f;
    {
        int nk = (seq - tid + 127) >> 7;
#pragma unroll 4
        for (int k = 0; k < nk; ++k) {
            int t  = tid + (k << 7);
            int r  = rb[t];
            int rp = (t == 0) ? 64 : rb[t - 1];
            float g = pb[(size_t)t * 64 + r] + trans[rp * 66 + r];
            if (t == seq - 1) g += trans[r * 66 + 65];
            gold += g;
        }
    }

    // ---- bootstrap: v_1 = exp(alpha_1 - m0) ----
    float alpha1 = pb[j] + trans[64 * 66 + j];
    float wm = warp_rmax(alpha1);          // max over this warp's 16 states
    if (lane == 0) fin[w] = wm;
    __syncthreads();
    float m0 = fmaxf(fmaxf(fin[0], fin[1]), fmaxf(fin[2], fin[3]));
    float v  = __expf(alpha1 - m0);

    int ks = 0;

    // prefetch pipeline: P_cur = exp(pred row t-1) consumed at step t
    float P_cur = __expf(pb[(size_t)min(1, seq - 1) * 64 + j]);
    float pv_a  = pb[(size_t)min(2, seq - 1) * 64 + j];
    float pv_b  = pb[(size_t)min(3, seq - 1) * 64 + j];

    int par = 0;
#pragma unroll 2
    for (int t = 2; t <= seq; ++t) {
        // publish v_{t-1} (one writer per state)
        if (h == 0) reinterpret_cast<float*>(e[par])[j] = v;

        // rotate prefetch BEFORE the sync so LDG/MUFU hide under it
        float Pn = __expf(pv_a);
        pv_a = pv_b;
        int tn = t + 2;
        int tc = tn < seq - 1 ? tn : seq - 1;
        pv_b = pb[(size_t)tc * 64 + j];

        __syncthreads();

        // uniform exact power-of-two scale from v_{t-1}[0]
        float m = reinterpret_cast<const float*>(e[par])[0];

        // partial s_j over floats [32h, 32h+32): 8x LDS.128 + 16x FFMA2
        const ulonglong2* evh =
            reinterpret_cast<const ulonglong2*>(e[par]) + 8 * h;
        ulonglong2 q0 = evh[0], q1 = evh[1], q2 = evh[2], q3 = evh[3];
        ulonglong2 q4 = evh[4], q5 = evh[5], q6 = evh[6], q7 = evh[7];
        u64 a0 = 0ull, a1 = 0ull, a2 = 0ull, a3 = 0ull;
        a0 = ffma2(q0.x, E2[0],  a0);
        a1 = ffma2(q0.y, E2[1],  a1);
        a2 = ffma2(q1.x, E2[2],  a2);
        a3 = ffma2(q1.y, E2[3],  a3);
        a0 = ffma2(q2.x, E2[4],  a0);
        a1 = ffma2(q2.y, E2[5],  a1);
        a2 = ffma2(q3.x, E2[6],  a2);
        a3 = ffma2(q3.y, E2[7],  a3);
        a0 = ffma2(q4.x, E2[8],  a0);
        a1 = ffma2(q4.y, E2[9],  a1);
        a2 = ffma2(q5.x, E2[10], a2);
        a3 = ffma2(q5.y, E2[11], a3);
        a0 = ffma2(q6.x, E2[12], a0);
        a1 = ffma2(q6.y, E2[13], a1);
        a2 = ffma2(q7.x, E2[14], a2);
        a3 = ffma2(q7.y, E2[15], a3);

        u64 s2 = fadd2(fadd2(a0, a2), fadd2(a1, a3));
        float slo, shi;
        asm("mov.b64 {%0, %1}, %2;" : "=f"(slo), "=f"(shi) : "l"(s2));
        float p_half = slo + shi;

        // combine halves (intra-warp pair l <-> l^16); both lanes get full s
        float p_oth = __shfl_xor_sync(0xffffffffu, p_half, 16);

        int ex = (__float_as_int(m) >> 23) - 127;
        ks += ex;
        float factor = P_cur * __int_as_float((127 - ex) << 23);

        v = (p_half + p_oth) * factor;

        P_cur = Pn;
        par ^= 1;
    }

    // ---- logZ and per-batch loss ----
    float wv = (h == 0) ? v * __expf(trans[j * 66 + 65]) : 0.0f;
    float sw = warp_rsum(wv);
    float gs = warp_rsum(gold);
    if (lane == 0) { fin[w] = sw; fin[4 + w] = gs; }
    __syncthreads();
    if (tid == 0) {
        float swt = (fin[0] + fin[1]) + (fin[2] + fin[3]);
        float gst = (fin[4] + fin[5]) + (fin[6] + fin[7]);
        double logZ = (double)m0
                    + 0.6931471805599453 * (double)ks
                    + (double)__logf(swt);
        g_partial[b] = logZ - (double)gst;
        __threadfence();
        int c = atomicAdd(&g_count, 1);
        s_last = (c == (int)gridDim.x - 1) ? 1 : 0;
    }
    __syncthreads();

    // ---- last CTA: deterministic fixed-order final reduction ----
    if (s_last) {
        __threadfence();
        double s = 0.0;
        for (int i = tid; i < B; i += 128) s += g_partial[i];
        red[tid] = s;
        __syncthreads();
#pragma unroll
        for (int wd = 64; wd > 0; wd >>= 1) {
            if (tid < wd) red[tid] += red[tid + wd];
            __syncthreads();
        }
        for (int i = tid; i < out_size; i += 128)
            out[i] = (i == 0) ? (float)red[0] : 0.0f;
        if (tid == 0) g_count = 0;   // reset for next graph replay
    }
}

extern "C" void kernel_launch(void* const* d_in, const int* in_sizes, int n_in,
                              void* d_out, int out_size)
{
    // Identify inputs by element count (robust to metadata ordering):
    //   trans = 66*66 = 4356, pred = largest, seq_len = smallest, ref = rest.
    int it = -1;
    for (int i = 0; i < n_in; ++i)
        if (in_sizes[i] == 66 * 66) { it = i; break; }
    int ip = -1, is = -1;
    for (int i = 0; i < n_in; ++i) {
        if (i == it) continue;
        if (ip < 0 || in_sizes[i] > in_sizes[ip]) ip = i;
        if (is < 0 || in_sizes[i] < in_sizes[is]) is = i;
    }
    int ir = -1;
    for (int i = 0; i < n_in; ++i)
        if (i != it && i != ip && i != is) { ir = i; break; }

    const float* pred  = (const float*)d_in[ip];
    const float* trans = (const float*)d_in[it];
    const int*   ref   = (const int*)d_in[ir];
    const int*   slen  = (const int*)d_in[is];

    const int B = in_sizes[is];
    const int T = in_sizes[ir] / B;

    crf_kernel<<<B, 128>>>(pred, trans, ref, slen, (float*)d_out, B, T, out_size);
}